// round 5
// baseline (speedup 1.0000x reference)
#include <cuda_runtime.h>
#include <math.h>

// iNGPDW: fused hash-grid encode + erf scaling + 40->64->64->13 SELU MLP.
// P=2 points per thread: each weight LDS.128 feeds both points (4 FFMA2),
// halving weight-LDS traffic per point. Activations staged as packed {p0,p1}
// u64 pairs in a 64-row shared buffer (column-private per thread, no barrier;
// rows reused h -> act1 -> act2 since each k-loop completes in registers
// before its writes). SELU uses expm1f (cancellation-safe).

constexpr int NLEV = 10;
constexpr int TBL  = 1 << 16;
constexpr int HIDN = 64;
constexpr int OUTD = 13;
constexpr int BLK  = 128;    // threads per block
constexpr int PPB  = 256;    // points per block (2 per thread)

struct ResParams { int res[NLEV]; };

typedef unsigned long long u64;

__device__ __forceinline__ u64 pk2(float lo, float hi) {
    u64 r; asm("mov.b64 %0, {%1, %2};" : "=l"(r) : "f"(lo), "f"(hi)); return r;
}
__device__ __forceinline__ u64 dup2(float v) {
    u64 r; asm("mov.b64 %0, {%1, %1};" : "=l"(r) : "f"(v)); return r;
}
__device__ __forceinline__ void upk2(u64 v, float& lo, float& hi) {
    asm("mov.b64 {%0, %1}, %2;" : "=f"(lo), "=f"(hi) : "l"(v));
}
__device__ __forceinline__ void fma2(u64& acc, u64 a, u64 b) {
    asm("fma.rn.f32x2 %0, %1, %2, %0;" : "+l"(acc) : "l"(a), "l"(b));
}

__device__ __forceinline__ float selu_f(float v) {
    const float sc = 1.0507009873554805f;
    const float al = 1.6732632423543772f;
    return v > 0.0f ? sc * v : sc * (al * expm1f(v));
}

__global__ __launch_bounds__(BLK, 2)
void ngp_fused5_kernel(const float*  __restrict__ gx,     // [N,3]
                       const float*  __restrict__ gcr,    // [N]
                       const float4* __restrict__ gtab,   // [NLEV*TBL] float4
                       const float*  __restrict__ gW1,    // [40,64]
                       const float*  __restrict__ gb1,    // [64]
                       const float*  __restrict__ gW2,    // [64,64]
                       const float*  __restrict__ gb2,    // [64]
                       const float*  __restrict__ gW3,    // [64,13]
                       const float*  __restrict__ gb3,    // [13]
                       float*        __restrict__ gout,   // [N,13]
                       int N, ResParams rp)
{
    __shared__ float sW1[40 * HIDN];      // natural [k][j]
    __shared__ float sW2[HIDN * HIDN];
    __shared__ float sW3[HIDN * 16];      // rows padded 13 -> 16
    __shared__ float sB1[HIDN];
    __shared__ float sB2[HIDN];
    __shared__ float sB3[16];
    extern __shared__ u64 sA[];           // [64][BLK] packed activations, 64 KB

    const int tid = threadIdx.x;
    for (int i = tid; i < 40 * HIDN; i += BLK) sW1[i] = gW1[i];
    for (int i = tid; i < HIDN * HIDN; i += BLK) sW2[i] = gW2[i];
    for (int i = tid; i < HIDN * 16; i += BLK) {
        int k = i >> 4, j = i & 15;
        sW3[i] = (j < OUTD) ? gW3[k * OUTD + j] : 0.0f;
    }
    if (tid < HIDN) { sB1[tid] = gb1[tid]; sB2[tid] = gb2[tid]; }
    if (tid < 16)   { sB3[tid] = (tid < OUTD) ? gb3[tid] : 0.0f; }
    __syncthreads();

    const int base = blockIdx.x * PPB;
    const int n0r = base + tid;
    const int n1r = base + BLK + tid;
    const bool v0 = (n0r < N), v1 = (n1r < N);
    const int n0 = v0 ? n0r : (N - 1);
    const int n1 = v1 ? n1r : (N - 1);

    const float p0x = gx[3 * n0 + 0], p0y = gx[3 * n0 + 1], p0z = gx[3 * n0 + 2];
    const float p1x = gx[3 * n1 + 0], p1y = gx[3 * n1 + 1], p1z = gx[3 * n1 + 2];
    const float crs0 = gcr[n0] * 0.5f;
    const float crs1 = gcr[n1] * 0.5f;

    // ---- encoding: both points per level, packed write to sA rows d*10+l ----
    #pragma unroll
    for (int l = 0; l < NLEV; l++) {
        const float rf = (float)rp.res[l];
        const float4* tb = gtab + (unsigned)(l * TBL);

        // point 0 setup
        const float a_xs0 = p0x * rf, a_xs1 = p0y * rf, a_xs2 = p0z * rf;
        const float a_fb0 = floorf(a_xs0), a_fb1 = floorf(a_xs1), a_fb2 = floorf(a_xs2);
        const float a_f0 = a_xs0 - a_fb0, a_f1 = a_xs1 - a_fb1, a_f2 = a_xs2 - a_fb2;
        const float a_g0 = 1.0f - a_f0, a_g1 = 1.0f - a_f1, a_g2 = 1.0f - a_f2;
        const unsigned a_c0 = (unsigned)a_fb0, a_c1 = (unsigned)a_fb1, a_c2 = (unsigned)a_fb2;
        const unsigned a_hx0 = a_c0,               a_hx1 = a_c0 + 1u;
        const unsigned a_hy0 = a_c1 * 2654435761u, a_hy1 = a_hy0 + 2654435761u;
        const unsigned a_hz0 = a_c2 * 805459861u,  a_hz1 = a_hz0 + 805459861u;
        const float a_wyz00 = a_g1 * a_g2, a_wyz01 = a_g1 * a_f2;
        const float a_wyz10 = a_f1 * a_g2, a_wyz11 = a_f1 * a_f2;

        // point 1 setup
        const float b_xs0 = p1x * rf, b_xs1 = p1y * rf, b_xs2 = p1z * rf;
        const float b_fb0 = floorf(b_xs0), b_fb1 = floorf(b_xs1), b_fb2 = floorf(b_xs2);
        const float b_f0 = b_xs0 - b_fb0, b_f1 = b_xs1 - b_fb1, b_f2 = b_xs2 - b_fb2;
        const float b_g0 = 1.0f - b_f0, b_g1 = 1.0f - b_f1, b_g2 = 1.0f - b_f2;
        const unsigned b_c0 = (unsigned)b_fb0, b_c1 = (unsigned)b_fb1, b_c2 = (unsigned)b_fb2;
        const unsigned b_hx0 = b_c0,               b_hx1 = b_c0 + 1u;
        const unsigned b_hy0 = b_c1 * 2654435761u, b_hy1 = b_hy0 + 2654435761u;
        const unsigned b_hz0 = b_c2 * 805459861u,  b_hz1 = b_hz0 + 805459861u;
        const float b_wyz00 = b_g1 * b_g2, b_wyz01 = b_g1 * b_f2;
        const float b_wyz10 = b_f1 * b_g2, b_wyz11 = b_f1 * b_f2;

        float A0 = 0.f, A1 = 0.f, A2 = 0.f, A3 = 0.f;
        float B0 = 0.f, B1 = 0.f, B2 = 0.f, B3 = 0.f;
        #pragma unroll
        for (int c = 0; c < 8; c++) {
            const unsigned ia = ((((c & 4) ? a_hx1 : a_hx0)
                                ^ ((c & 2) ? a_hy1 : a_hy0)
                                ^ ((c & 1) ? a_hz1 : a_hz0)) & (unsigned)(TBL - 1));
            const unsigned ib = ((((c & 4) ? b_hx1 : b_hx0)
                                ^ ((c & 2) ? b_hy1 : b_hy0)
                                ^ ((c & 1) ? b_hz1 : b_hz0)) & (unsigned)(TBL - 1));
            const float4 ta = __ldg(&tb[ia]);
            const float4 tbv = __ldg(&tb[ib]);
            const float wyza = (c & 2) ? ((c & 1) ? a_wyz11 : a_wyz10)
                                       : ((c & 1) ? a_wyz01 : a_wyz00);
            const float wyzb = (c & 2) ? ((c & 1) ? b_wyz11 : b_wyz10)
                                       : ((c & 1) ? b_wyz01 : b_wyz00);
            const float wa = ((c & 4) ? a_f0 : a_g0) * wyza;
            const float wb = ((c & 4) ? b_f0 : b_g0) * wyzb;
            A0 = fmaf(wa, ta.x, A0);  A1 = fmaf(wa, ta.y, A1);
            A2 = fmaf(wa, ta.z, A2);  A3 = fmaf(wa, ta.w, A3);
            B0 = fmaf(wb, tbv.x, B0); B1 = fmaf(wb, tbv.y, B1);
            B2 = fmaf(wb, tbv.z, B2); B3 = fmaf(wb, tbv.w, B3);
        }
        float scal0, scal1;
        if (l == 0) {
            scal0 = 1.0f; scal1 = 1.0f;   // erf(1/sqrt(1e-12)) == 1 in fp32
        } else {
            scal0 = erff(rsqrtf(fmaxf((8.0f * (float)l) * crs0, 1e-12f)));
            scal1 = erff(rsqrtf(fmaxf((8.0f * (float)l) * crs1, 1e-12f)));
        }
        sA[(0 * 10 + l) * BLK + tid] = pk2(A0 * scal0, B0 * scal1);
        sA[(1 * 10 + l) * BLK + tid] = pk2(A1 * scal0, B1 * scal1);
        sA[(2 * 10 + l) * BLK + tid] = pk2(A2 * scal0, B2 * scal1);
        sA[(3 * 10 + l) * BLK + tid] = pk2(A3 * scal0, B3 * scal1);
    }

    // ---- layer 1: 40 -> 64, SELU. acc for both points, full 64 j. ----
    {
        u64 acc0[32], acc1[32];
        const u64* bi = reinterpret_cast<const u64*>(&sB1[0]);
        #pragma unroll
        for (int q = 0; q < 32; q++) { acc0[q] = bi[q]; acc1[q] = bi[q]; }

        #pragma unroll 8
        for (int k = 0; k < 40; k++) {
            float h0, h1; upk2(sA[k * BLK + tid], h0, h1);
            const u64 d0 = dup2(h0), d1 = dup2(h1);
            const ulonglong2* wr = reinterpret_cast<const ulonglong2*>(&sW1[k * HIDN]);
            #pragma unroll
            for (int q2 = 0; q2 < 16; q2++) {
                const ulonglong2 w = wr[q2];
                fma2(acc0[2 * q2 + 0], d0, w.x);
                fma2(acc0[2 * q2 + 1], d0, w.y);
                fma2(acc1[2 * q2 + 0], d1, w.x);
                fma2(acc1[2 * q2 + 1], d1, w.y);
            }
        }
        // h rows fully consumed -> safe to overwrite with act1
        #pragma unroll
        for (int q = 0; q < 32; q++) {
            float a0l, a0h, a1l, a1h;
            upk2(acc0[q], a0l, a0h);
            upk2(acc1[q], a1l, a1h);
            sA[(2 * q + 0) * BLK + tid] = pk2(selu_f(a0l), selu_f(a1l));
            sA[(2 * q + 1) * BLK + tid] = pk2(selu_f(a0h), selu_f(a1h));
        }
    }

    // ---- layer 2: 64 -> 64, SELU ----
    {
        u64 acc0[32], acc1[32];
        const u64* bi = reinterpret_cast<const u64*>(&sB2[0]);
        #pragma unroll
        for (int q = 0; q < 32; q++) { acc0[q] = bi[q]; acc1[q] = bi[q]; }

        #pragma unroll 8
        for (int k = 0; k < HIDN; k++) {
            float h0, h1; upk2(sA[k * BLK + tid], h0, h1);
            const u64 d0 = dup2(h0), d1 = dup2(h1);
            const ulonglong2* wr = reinterpret_cast<const ulonglong2*>(&sW2[k * HIDN]);
            #pragma unroll
            for (int q2 = 0; q2 < 16; q2++) {
                const ulonglong2 w = wr[q2];
                fma2(acc0[2 * q2 + 0], d0, w.x);
                fma2(acc0[2 * q2 + 1], d0, w.y);
                fma2(acc1[2 * q2 + 0], d1, w.x);
                fma2(acc1[2 * q2 + 1], d1, w.y);
            }
        }
        #pragma unroll
        for (int q = 0; q < 32; q++) {
            float a0l, a0h, a1l, a1h;
            upk2(acc0[q], a0l, a0h);
            upk2(acc1[q], a1l, a1h);
            sA[(2 * q + 0) * BLK + tid] = pk2(selu_f(a0l), selu_f(a1l));
            sA[(2 * q + 1) * BLK + tid] = pk2(selu_f(a0h), selu_f(a1h));
        }
    }

    // ---- layer 3: 64 -> 13, linear ----
    {
        u64 acc0[7], acc1[7];
        const u64* bi = reinterpret_cast<const u64*>(&sB3[0]);
        #pragma unroll
        for (int q = 0; q < 7; q++) { acc0[q] = bi[q]; acc1[q] = bi[q]; }

        #pragma unroll 8
        for (int k = 0; k < HIDN; k++) {
            float h0, h1; upk2(sA[k * BLK + tid], h0, h1);
            const u64 d0 = dup2(h0), d1 = dup2(h1);
            const ulonglong2* wr = reinterpret_cast<const ulonglong2*>(&sW3[k * 16]);
            #pragma unroll
            for (int q2 = 0; q2 < 4; q2++) {
                const ulonglong2 w = wr[q2];
                fma2(acc0[2 * q2 + 0], d0, w.x);
                fma2(acc1[2 * q2 + 0], d1, w.x);
                if (q2 < 3) {
                    fma2(acc0[2 * q2 + 1], d0, w.y);
                    fma2(acc1[2 * q2 + 1], d1, w.y);
                }
            }
        }
        float s0[14], s1[14];
        #pragma unroll
        for (int q = 0; q < 7; q++) {
            upk2(acc0[q], s0[2 * q], s0[2 * q + 1]);
            upk2(acc1[q], s1[2 * q], s1[2 * q + 1]);
        }
        if (v0) {
            float* op = gout + (size_t)n0 * OUTD;
            #pragma unroll
            for (int j = 0; j < OUTD; j++) op[j] = s0[j];
        }
        if (v1) {
            float* op = gout + (size_t)n1 * OUTD;
            #pragma unroll
            for (int j = 0; j < OUTD; j++) op[j] = s1[j];
        }
    }
}

extern "C" void kernel_launch(void* const* d_in, const int* in_sizes, int n_in,
                              void* d_out, int out_size) {
    const float*  x   = (const float*)d_in[0];
    const float*  cr  = (const float*)d_in[1];
    const float4* tab = (const float4*)d_in[2];
    const float*  W1  = (const float*)d_in[3];
    const float*  b1  = (const float*)d_in[4];
    const float*  W2  = (const float*)d_in[5];
    const float*  b2  = (const float*)d_in[6];
    const float*  W3  = (const float*)d_in[7];
    const float*  b3  = (const float*)d_in[8];
    float* out = (float*)d_out;

    const int N = in_sizes[0] / 3;

    // Reference resolutions, identical libm double sequence.
    ResParams rp;
    const double B = exp((log(16.0 * pow(2.0, 10.0)) - log(16.0)) / 9.0);
    for (int l = 0; l < NLEV; l++) {
        rp.res[l] = (int)floor(16.0 * pow(B, (double)l));
    }

    const int dynSmem = HIDN * BLK * (int)sizeof(u64);   // 64 KB
    static bool attr_set = false;
    if (!attr_set) {
        cudaFuncSetAttribute(ngp_fused5_kernel,
                             cudaFuncAttributeMaxDynamicSharedMemorySize, dynSmem);
        attr_set = true;
    }

    const int blocks = (N + PPB - 1) / PPB;
    ngp_fused5_kernel<<<blocks, BLK, dynSmem>>>(
        x, cr, tab, W1, b1, W2, b2, W3, b3, out, N, rp);
}